// round 7
// baseline (speedup 1.0000x reference)
#include <cuda_runtime.h>
#include <math_constants.h>

#define NM 1024
#define HGT 256
#define WID 256
#define HW 65536
#define NPART 4
#define NFB 64          // blocks in the fused nms+fixup kernel
#define FIX_PARTS 16    // 16KB zero-fill units per missed mask

#define MASK_THR 0.0f
#define STAB_OFF 1.0f
#define IOU_THR 0.88f
#define STAB_THR 0.95f
#define NMS_THR 0.7f

// Scratch (static device globals -- no runtime allocation)
__device__ int2 g_cnt[NPART * NM];        // (hi, lo) partials
__device__ int4 g_bxp[NPART * NM];        // (L, R, T, B) partials
__device__ unsigned g_supmask[NM * 32];   // fallback path only (M > 352); value-identical across blocks

// ---------------------------------------------------------------------------
// Row sweep, templated on candidate status. Candidates (iou > IOU_THR) get a
// speculative sigmoid(v)*iou written to out -- exactly the final value if the
// mask survives NMS (gated = iou when kept). Non-candidates can never be kept,
// so they get zeros. Either way pass 1 is one read stream + one write stream.
// ---------------------------------------------------------------------------
template<bool CAND>
__device__ __forceinline__ void sweep(const float* __restrict__ base,
                                      float4* __restrict__ ob,
                                      int y0, int lane, float gi,
                                      int& hi, int& lo, int& top, int& bot,
                                      unsigned& colmask) {
    #pragma unroll 4
    for (int r = 0; r < 8; r++) {
        const int y = y0 + r;
        const float4* row = reinterpret_cast<const float4*>(base + (size_t)y * WID);
        float4 a = __ldcs(&row[lane]);
        float4 b = __ldcs(&row[lane + 32]);

        float4 oa, obv;
        if (CAND) {
            oa.x = __fdividef(gi, 1.f + __expf(-a.x));
            oa.y = __fdividef(gi, 1.f + __expf(-a.y));
            oa.z = __fdividef(gi, 1.f + __expf(-a.z));
            oa.w = __fdividef(gi, 1.f + __expf(-a.w));
            obv.x = __fdividef(gi, 1.f + __expf(-b.x));
            obv.y = __fdividef(gi, 1.f + __expf(-b.y));
            obv.z = __fdividef(gi, 1.f + __expf(-b.z));
            obv.w = __fdividef(gi, 1.f + __expf(-b.w));
        } else {
            oa  = make_float4(0.f, 0.f, 0.f, 0.f);
            obv = make_float4(0.f, 0.f, 0.f, 0.f);
        }
        __stcs(&ob[(size_t)y * (WID / 4) + lane], oa);
        __stcs(&ob[(size_t)y * (WID / 4) + lane + 32], obv);

        unsigned rm = 0;
        float va[8] = {a.x, a.y, a.z, a.w, b.x, b.y, b.z, b.w};
        #pragma unroll
        for (int c = 0; c < 8; c++) {
            float f = va[c];
            hi += (f > (MASK_THR + STAB_OFF)) ? 1 : 0;
            lo += (f > (MASK_THR - STAB_OFF)) ? 1 : 0;
            rm |= (f > MASK_THR) ? (1u << c) : 0u;
        }
        if (rm) {
            top = min(top, y);
            bot = y;                 // rows ascend -> last positive row wins
            colmask |= rm;
        }
    }
}

// ---------------------------------------------------------------------------
// Kernel 1: per-mask stats fused with speculative output write. Block
// (part, n) covers rows [part*64, part*64+64); 8 warps x 8 rows each.
// ---------------------------------------------------------------------------
__global__ __launch_bounds__(256) void stats_spec_kernel(const float* __restrict__ logits,
                                                         const float* __restrict__ iou,
                                                         float* __restrict__ out) {
    const int part = blockIdx.x;
    const int n = blockIdx.y;
    const int warp = threadIdx.x >> 5;
    const int lane = threadIdx.x & 31;
    const size_t mbase = (size_t)n * HW;
    const float* base = logits + mbase;
    float4* ob = reinterpret_cast<float4*>(out + mbase);
    const int y0 = part * 64 + warp * 8;
    const float gi = iou[n];

    int hi = 0, lo = 0;
    int top = HGT, bot = -1;
    unsigned colmask = 0;   // bits 0-3: cols lane*4+c ; bits 4-7: cols lane*4+128+c

    if (gi > IOU_THR)
        sweep<true>(base, ob, y0, lane, gi, hi, lo, top, bot, colmask);
    else
        sweep<false>(base, ob, y0, lane, gi, hi, lo, top, bot, colmask);

    // Resolve per-thread x extents from the column mask.
    int left = WID, right = -1;
    unsigned lowm = colmask & 0xFu, highm = colmask >> 4;
    if (lowm)  left = lane * 4 + (__ffs(lowm) - 1);
    else if (highm) left = lane * 4 + 128 + (__ffs(highm) - 1);
    if (highm) right = lane * 4 + 128 + (31 - __clz(highm));
    else if (lowm) right = lane * 4 + (31 - __clz(lowm));

    // Warp-level butterfly reduction.
    #pragma unroll
    for (int o = 16; o; o >>= 1) {
        hi   += __shfl_xor_sync(0xffffffffu, hi, o);
        lo   += __shfl_xor_sync(0xffffffffu, lo, o);
        left  = min(left,  __shfl_xor_sync(0xffffffffu, left, o));
        right = max(right, __shfl_xor_sync(0xffffffffu, right, o));
        top   = min(top,   __shfl_xor_sync(0xffffffffu, top, o));
        bot   = max(bot,   __shfl_xor_sync(0xffffffffu, bot, o));
    }

    __shared__ int s[8][6];
    if (lane == 0) {
        s[warp][0] = hi; s[warp][1] = lo;
        s[warp][2] = left; s[warp][3] = right;
        s[warp][4] = top; s[warp][5] = bot;
    }
    __syncthreads();
    if (threadIdx.x == 0) {
        int Hi = 0, Lo = 0, L = WID, R = -1, T = HGT, B = -1;
        #pragma unroll
        for (int w = 0; w < 8; w++) {
            Hi += s[w][0]; Lo += s[w][1];
            L = min(L, s[w][2]); R = max(R, s[w][3]);
            T = min(T, s[w][4]); B = max(B, s[w][5]);
        }
        const int o = part * NM + n;
        g_cnt[o] = make_int2(Hi, Lo);
        g_bxp[o] = make_int4(L, R, T, B);
    }
}

// ---------------------------------------------------------------------------
// Kernel 2 (fused): NMS + fixup. NFB blocks x 1024 threads. EVERY block
// redundantly computes the identical NMS from global partials (deterministic:
// ballot-compaction everywhere, no atomics) -- a few us of shared-mem loops,
// run in parallel across blocks, so no inter-block sync is needed. Each block
// then zero-fills its blockIdx-strided share of the mis-speculated masks.
// Block 0 additionally writes the keep/boxes output tail.
// ---------------------------------------------------------------------------
__global__ __launch_bounds__(1024) void nms_fix_kernel(const float* __restrict__ iou,
                                                       float* __restrict__ out) {
    const int tid = threadIdx.x;
    const int lane = tid & 31;
    const int wid = tid >> 5;
    float* out_tail = out + (size_t)NM * HW;

    __shared__ union {
        struct { float4 bx[NM]; float cs[NM]; int cid[NM]; } p1;      // 24KB
        struct { unsigned sup[4096]; float4 sbx[512]; } p2;           // 24KB (aliases p1)
    } u;
    __shared__ int s_sorted[NM];
    __shared__ int s_miss[NM];
    __shared__ unsigned char s_keep[NM];
    __shared__ int s_wcnt[32];
    __shared__ int s_mcnt[32];

    float myiou = iou[tid];

    // Combine the 4 stats partials (vectorized).
    int Hi = 0, Lo = 0, L = WID, R = -1, T = HGT, B = -1;
    #pragma unroll
    for (int p = 0; p < NPART; p++) {
        const int o = p * NM + tid;
        int2 cl = g_cnt[o];
        int4 bx = g_bxp[o];
        Hi += cl.x; Lo += cl.y;
        L = min(L, bx.x); R = max(R, bx.y);
        T = min(T, bx.z); B = max(B, bx.w);
    }
    bool nonempty = (B >= 0);
    float4 bf = nonempty
        ? make_float4((float)L, (float)T, (float)R, (float)B)
        : make_float4(0.f, 0.f, 0.f, 0.f);
    u.p1.bx[tid] = bf;

    float stab = (float)Hi / fmaxf((float)Lo, 1.0f);
    bool cand = (myiou > IOU_THR);
    bool valid = cand && (stab >= STAB_THR);
    s_keep[tid] = 0;

    // Compaction: stable (tid-order) pack of valid entries.
    unsigned bal = __ballot_sync(0xffffffffu, valid);
    if (lane == 0) s_wcnt[wid] = __popc(bal);
    __syncthreads();
    int M = 0, wbase = 0;
    #pragma unroll
    for (int w = 0; w < 32; w++) {
        int cw = s_wcnt[w];
        M += cw;
        if (w < wid) wbase += cw;
    }
    int c = -1;
    if (valid) {
        c = wbase + __popc(bal & ((1u << lane) - 1u));
        u.p1.cs[c] = myiou;
        u.p1.cid[c] = tid;
    }
    __syncthreads();

    // Rank among valid entries only: score desc, ties -> lower original index
    // (compaction is tid-stable, so j<c encodes the tie rule).
    if (valid) {
        int r = 0;
        float si = myiou;
        for (int j = 0; j < M; j++) {
            float sj = u.p1.cs[j];
            r += ((sj > si) || (sj == si && j < c)) ? 1 : 0;
        }
        s_sorted[r] = tid;
    }
    __syncthreads();

    if (M > 0 && M <= 352) {
        const int nwords = (M + 31) >> 5;
        if (tid < M) u.p2.sbx[tid] = u.p1.bx[s_sorted[tid]];  // sbx aliases cs/cid (dead)
        __syncthreads();  // sbx ready; p1.bx reads done before sup overwrites it

        if (tid < nwords * 32) {
            float4 cb = (tid < M) ? u.p2.sbx[tid] : make_float4(0.f, 0.f, 0.f, 0.f);
            float areaB = fmaxf(cb.z - cb.x, 0.f) * fmaxf(cb.w - cb.y, 0.f);
            for (int i = 0; i < M; i++) {
                float4 ib = u.p2.sbx[i];
                float areaA = fmaxf(ib.z - ib.x, 0.f) * fmaxf(ib.w - ib.y, 0.f);
                float ix = fmaxf(fminf(ib.z, cb.z) - fmaxf(ib.x, cb.x), 0.f);
                float iy = fmaxf(fminf(ib.w, cb.w) - fmaxf(ib.y, cb.y), 0.f);
                float inter = ix * iy;
                float iouv = inter / fmaxf(areaA + areaB - inter, 1e-6f);
                bool bit = (tid < M) && (iouv > NMS_THR);
                unsigned bl = __ballot_sync(0xffffffffu, bit);
                if (lane == 0) u.p2.sup[i * nwords + wid] = bl;
            }
        }
        __syncthreads();

        // Single-warp greedy over the shared bitmask.
        if (tid < 32) {
            unsigned removed = 0;
            for (int i = 0; i < M; i++) {
                unsigned w = __shfl_sync(0xffffffffu, removed, i >> 5);
                if (!((w >> (i & 31)) & 1u)) {
                    removed |= (tid < nwords) ? u.p2.sup[i * nwords + tid] : 0u;
                    if (tid == 0) s_keep[s_sorted[i]] = 1;
                }
            }
        }
    } else if (M > 0) {
        // Fallback: global matrix, full 32-word rows (rarely hit). Multiple
        // blocks write identical values -> benign.
        float4 mb = (tid < M) ? u.p1.bx[s_sorted[tid]] : make_float4(0.f, 0.f, 0.f, 0.f);
        float areaB = fmaxf(mb.z - mb.x, 0.f) * fmaxf(mb.w - mb.y, 0.f);
        for (int i = 0; i < M; i++) {
            float4 ib = u.p1.bx[s_sorted[i]];
            float areaA = fmaxf(ib.z - ib.x, 0.f) * fmaxf(ib.w - ib.y, 0.f);
            float ix = fmaxf(fminf(ib.z, mb.z) - fmaxf(ib.x, mb.x), 0.f);
            float iy = fmaxf(fminf(ib.w, mb.w) - fmaxf(ib.y, mb.y), 0.f);
            float inter = ix * iy;
            float iouv = inter / fmaxf(areaA + areaB - inter, 1e-6f);
            bool bit = (tid < M) && (iouv > NMS_THR);
            unsigned bl = __ballot_sync(0xffffffffu, bit);
            if (lane == 0) g_supmask[i * 32 + wid] = bl;
        }
        __syncthreads();
        if (tid < 32) {
            unsigned removed = 0;
            for (int i = 0; i < M; i++) {
                unsigned w = __shfl_sync(0xffffffffu, removed, i >> 5);
                if (!((w >> (i & 31)) & 1u)) {
                    removed |= g_supmask[i * 32 + tid];
                    if (tid == 0) s_keep[s_sorted[i]] = 1;
                }
            }
        }
    }
    __syncthreads();

    bool kp = (s_keep[tid] != 0);
    if (blockIdx.x == 0) {
        out_tail[tid] = kp ? 1.f : 0.f;              // keep[N] as float
        float* ob = out_tail + NM + (size_t)tid * 4; // boxes [N,4] = (x0,y0,x1,y1)
        ob[0] = bf.x; ob[1] = bf.y; ob[2] = bf.z; ob[3] = bf.w;
    }

    // Deterministic (tid-stable, ballot-based) compaction of the miss list --
    // identical across all blocks, so the blockIdx-strided work partition is
    // consistent without any inter-block communication.
    bool miss = cand && !kp;
    unsigned mbal = __ballot_sync(0xffffffffu, miss);
    if (lane == 0) s_mcnt[wid] = __popc(mbal);
    __syncthreads();
    int cnt = 0, mbase = 0;
    #pragma unroll
    for (int w = 0; w < 32; w++) {
        int cw = s_mcnt[w];
        cnt += cw;
        if (w < wid) mbase += cw;
    }
    if (miss)
        s_miss[mbase + __popc(mbal & ((1u << lane) - 1u))] = tid;
    __syncthreads();

    // Zero-fill: unit = one 16KB sub-tile (1024 threads x float4).
    const float4 z = make_float4(0.f, 0.f, 0.f, 0.f);
    const int units = cnt * FIX_PARTS;
    for (int uu = blockIdx.x; uu < units; uu += NFB) {
        const int n = s_miss[uu >> 4];
        const int p = uu & (FIX_PARTS - 1);
        float4* o4 = reinterpret_cast<float4*>(out + (size_t)n * HW + (size_t)p * (HW / FIX_PARTS));
        __stcs(&o4[tid], z);
    }
}

extern "C" void kernel_launch(void* const* d_in, const int* in_sizes, int n_in,
                              void* d_out, int out_size) {
    const float* logits = (const float*)d_in[0];
    const float* iou = (const float*)d_in[1];
    if (n_in >= 2 && in_sizes[0] == NM && in_sizes[1] == NM * HW) {
        // Defensive against input-order swap.
        logits = (const float*)d_in[1];
        iou = (const float*)d_in[0];
    }
    float* out = (float*)d_out;

    dim3 sgrid(NPART, NM);
    stats_spec_kernel<<<sgrid, 256>>>(logits, iou, out);
    nms_fix_kernel<<<NFB, 1024>>>(iou, out);
}